// round 16
// baseline (speedup 1.0000x reference)
#include <cuda_runtime.h>
#include <cuda_bf16.h>
#include <cstdint>
#include <cstddef>

#define NNODES 8192
#define DDIM   16
#define BATCH  4
#define NC     64                       // B*D output columns
#define MT     128                      // M tile
#define KT     32                       // K per stage
#define NKU    256                      // k-units per m-tile (8192/32)
#define NMT    64                       // m-tiles
#define NCTA   296                      // 148 SMs x 2 CTAs, exact fit
#define SLOTS  6                        // max k-segments per m-tile
#define STAGES 4

#define AROWF  40                       // A smem row: 32 fp32 + 8 pad (160B)
#define AROWB  160
#define XROWB  80                       // X smem row: 64B bf16 + 16 pad
#define A_BYTES (MT * AROWB)            // 20480
#define X_BYTES (NC * XROWB)            // 5120
#define STAGE_BYTES (A_BYTES + X_BYTES) // 25600
#define SMEM_TOTAL  (STAGES * STAGE_BYTES) // 102400

#define W1TS 20   // transposed W1 row stride (16 used, 16B-aligned)

__device__ __align__(128) __nv_bfloat16 g_XT[NC * NNODES];     // 1 MB bf16
__device__ __align__(128) float g_part[SLOTS * NNODES * NC];   // 12.6 MB

// CTA c covers global units [s(c), s(c+1)), s(c) = floor(2048*c/37)
__device__ __forceinline__ int sched_start(int c) { return (c * 2048) / 37; }
__device__ __forceinline__ int sched_cfirst(int m) { return ((9472 * m + 2084) >> 11) - 1; }
__device__ __forceinline__ int sched_clast(int m) { return ((37 * (m + 1) + 7) >> 3) - 1; }

// ---- helpers ----
__device__ __forceinline__ uint32_t smem_u32(const void* p) {
    uint32_t a;
    asm("{ .reg .u64 t; cvta.to.shared.u64 t, %1; cvt.u32.u64 %0, t; }" : "=r"(a) : "l"(p));
    return a;
}
__device__ __forceinline__ void cp_async16(uint32_t smem_dst, const void* gmem_src) {
    asm volatile("cp.async.cg.shared.global [%0], [%1], 16;" :: "r"(smem_dst), "l"(gmem_src));
}
#define CP_COMMIT() asm volatile("cp.async.commit_group;" ::: "memory")

__device__ __forceinline__ float tanh_fast(float x) {
    float r;
    asm("tanh.approx.f32 %0, %1;" : "=f"(r) : "f"(x));
    return r;
}

__device__ __forceinline__ uint32_t bf2(float lo, float hi) {
    __nv_bfloat162 v = __float22bfloat162_rn(make_float2(lo, hi));
    return *(uint32_t*)&v;
}

__device__ __forceinline__ void mma_bf16(float* c, const uint32_t* a, const uint32_t* b) {
    asm volatile(
        "mma.sync.aligned.m16n8k16.row.col.f32.bf16.bf16.f32 "
        "{%0,%1,%2,%3}, {%4,%5,%6,%7}, {%8,%9}, {%0,%1,%2,%3};"
        : "+f"(c[0]), "+f"(c[1]), "+f"(c[2]), "+f"(c[3])
        : "r"(a[0]), "r"(a[1]), "r"(a[2]), "r"(a[3]), "r"(b[0]), "r"(b[1]));
}

// ---------------- kernel 1: transpose (-> g_XT) + fused DIFFUSION net ----------------
// 128 CTAs; CTA (b, m0) handles 256 nodes. tile[d][m] = h[b][m0+m][d] feeds both
// the bf16 transpose and the diffusion MLP (y = h row).
__global__ void __launch_bounds__(256) transpose_diff_kernel(
    const float* __restrict__ h, const float* __restrict__ t,
    const float* __restrict__ W1g, const float* __restrict__ b1g,
    const float* __restrict__ W2g, const float* __restrict__ b2g,
    float* __restrict__ out) {
    __shared__ float tile[16][258];
    __shared__ __align__(16) float sW1gT[64 * W1TS];
    __shared__ __align__(16) float sW2g[64 * 16];
    __shared__ float sbzg[64], sb2g[16];
    int tid = threadIdx.x;
    int b  = blockIdx.x >> 5;
    int m0 = (blockIdx.x & 31) << 8;    // 256 rows per block

    // stage g-net weights
    for (int i = tid; i < 16 * 64; i += 256) {
        int j = i & 63, r = i >> 6;
        sW1gT[j * W1TS + r] = W1g[i];
    }
    for (int i = tid; i < 64 * 16; i += 256) sW2g[i] = W2g[i];
    float tv = t[0];
    if (tid < 64) sbzg[tid] = fmaf(tv, W1g[16 * 64 + tid], b1g[tid]);
    if (tid < 16) sb2g[tid] = b2g[tid];

    const float4* src = (const float4*)(h + (size_t)b * (NNODES * DDIM) + (size_t)m0 * DDIM);
    float4 v[4];
#pragma unroll
    for (int i = 0; i < 4; i++) v[i] = src[i * 256 + tid];
#pragma unroll
    for (int i = 0; i < 4; i++) {
        int j = i * 256 + tid;
        int m = j >> 2, d0 = (j & 3) * 4;
        tile[d0 + 0][m] = v[i].x;
        tile[d0 + 1][m] = v[i].y;
        tile[d0 + 2][m] = v[i].z;
        tile[d0 + 3][m] = v[i].w;
    }
    __syncthreads();
    // bf16 transpose out
#pragma unroll
    for (int i = 0; i < 8; i++) {
        int j = i * 256 + tid;
        int d = j >> 7, mp = j & 127;
        float2 p = *(const float2*)&tile[d][2 * mp];
        __nv_bfloat162 w = __float22bfloat162_rn(p);
        *(__nv_bfloat162*)(g_XT + (size_t)(b * 16 + d) * NNODES + m0 + 2 * mp) = w;
    }

    // ---- diffusion for node n = m0 + tid ----
    float y[16];
#pragma unroll
    for (int d = 0; d < 16; d++) y[d] = tile[d][tid];

    float dacc[16];
#pragma unroll
    for (int d = 0; d < 16; d++) dacc[d] = sb2g[d];

#pragma unroll 4
    for (int j = 0; j < 64; j++) {
        const float4* wgr = (const float4*)(sW1gT + j * W1TS);
        float4 w0 = wgr[0], w1 = wgr[1], w2 = wgr[2], w3 = wgr[3];
        float za = fmaf(y[0], w0.x, fmaf(y[1], w0.y, fmaf(y[2], w0.z, y[3] * w0.w)));
        float zb = fmaf(y[4], w1.x, fmaf(y[5], w1.y, fmaf(y[6], w1.z, y[7] * w1.w)));
        float zc = fmaf(y[8], w2.x, fmaf(y[9], w2.y, fmaf(y[10], w2.z, y[11] * w2.w)));
        float zd = fmaf(y[12], w3.x, fmaf(y[13], w3.y, fmaf(y[14], w3.z, y[15] * w3.w)));
        float zg = (za + zb) + (zc + zd) + sbzg[j];
        float ag = fmaf(0.5f, tanh_fast(0.5f * zg), 0.5f);   // sigmoid via MUFU tanh

        const float4* w2r = (const float4*)(sW2g + j * 16);
#pragma unroll
        for (int q = 0; q < 4; q++) {
            float4 cg = w2r[q];
            dacc[4 * q + 0] = fmaf(ag, cg.x, dacc[4 * q + 0]);
            dacc[4 * q + 1] = fmaf(ag, cg.y, dacc[4 * q + 1]);
            dacc[4 * q + 2] = fmaf(ag, cg.z, dacc[4 * q + 2]);
            dacc[4 * q + 3] = fmaf(ag, cg.w, dacc[4 * q + 3]);
        }
    }

    size_t o0 = (size_t)b * NNODES * DDIM + (size_t)(m0 + tid) * DDIM;
    float4* og = (float4*)(out + (size_t)BATCH * NNODES * DDIM + o0);
#pragma unroll
    for (int k = 0; k < 4; k++) {
        // 0.1*sigmoid(z) = 0.05*tanh(0.5z) + 0.05
        float g0 = fmaf(0.05f, tanh_fast(0.5f * dacc[4 * k + 0]), 0.05f);
        float g1 = fmaf(0.05f, tanh_fast(0.5f * dacc[4 * k + 1]), 0.05f);
        float g2 = fmaf(0.05f, tanh_fast(0.5f * dacc[4 * k + 2]), 0.05f);
        float g3 = fmaf(0.05f, tanh_fast(0.5f * dacc[4 * k + 3]), 0.05f);
        og[k] = make_float4(g0, g1, g2, g3);
    }
}

// ---------------- kernel 2: balanced bf16 mma GEMM -> g_part (R14-identical) ----------------
__global__ void __launch_bounds__(256, 2) gemm_kernel(const float* __restrict__ A) {
    extern __shared__ char smem[];
    uint32_t sb = smem_u32(smem);

    int tid = threadIdx.x;
    int c   = blockIdx.x;
    int gs  = sched_start(c);
    int ge  = sched_start(c + 1);

    int lane = tid & 31, wid = tid >> 5;
    int wm = wid & 3, wn = wid >> 2;
    int qrow = lane >> 2, qcol = lane & 3;

    uint32_t offA[4]; size_t aoffA[4];
#pragma unroll
    for (int i = 0; i < 4; i++) {
        int q = i * 256 + tid;
        int row = q >> 3, c16 = q & 7;
        offA[i] = (uint32_t)(row * AROWB + c16 * 16);
        aoffA[i] = (size_t)row * NNODES + (size_t)c16 * 4;
    }
    uint32_t offX; size_t xoff;
    {
        int row = tid >> 2, c16 = tid & 3;
        offX = (uint32_t)(row * XROWB + c16 * 16);
        xoff = (size_t)row * NNODES + (size_t)c16 * 8;
    }

#pragma unroll
    for (int p = 0; p < STAGES - 1; p++) {
        int g = gs + p;
        int m = g >> 8, k0 = (g & 255) * KT;
        size_t abase = (size_t)m * MT * NNODES + k0;
        uint32_t ab = sb + (g & 3) * STAGE_BYTES;
#pragma unroll
        for (int i = 0; i < 4; i++) cp_async16(ab + offA[i], A + abase + aoffA[i]);
        cp_async16(ab + A_BYTES + offX, g_XT + xoff + k0);
        CP_COMMIT();
    }

    float acc[2][4][4];
#pragma unroll
    for (int mf = 0; mf < 2; mf++)
#pragma unroll
        for (int nf = 0; nf < 4; nf++)
#pragma unroll
            for (int r = 0; r < 4; r++) acc[mf][nf][r] = 0.0f;

    const int arow0 = wm * 32 + qrow;
    const int xrow0 = wn * 32 + qrow;
    int cur_m = gs >> 8;

    for (int g = gs; g < ge; g++) {
        asm volatile("cp.async.wait_group %0;" :: "n"(STAGES - 2) : "memory");
        __syncthreads();

        int gn = g + STAGES - 1;
        if (gn < ge) {
            int m = gn >> 8, k0 = (gn & 255) * KT;
            size_t abase = (size_t)m * MT * NNODES + k0;
            uint32_t ab = sb + (gn & 3) * STAGE_BYTES;
#pragma unroll
            for (int i = 0; i < 4; i++) cp_async16(ab + offA[i], A + abase + aoffA[i]);
            cp_async16(ab + A_BYTES + offX, g_XT + xoff + k0);
        }
        CP_COMMIT();

        const float* As = (const float*)(smem + (g & 3) * STAGE_BYTES);
        const char*  Xs = smem + (g & 3) * STAGE_BYTES + A_BYTES;
#pragma unroll
        for (int kk = 0; kk < 2; kk++) {
            int kb = kk * 16;
            uint32_t a[2][4];
#pragma unroll
            for (int mf = 0; mf < 2; mf++) {
                int r = arow0 + mf * 16;
                float2 p0 = *(const float2*)(As + (size_t)r * AROWF + kb + 2 * qcol);
                float2 p1 = *(const float2*)(As + (size_t)(r + 8) * AROWF + kb + 2 * qcol);
                float2 p2 = *(const float2*)(As + (size_t)r * AROWF + kb + 2 * qcol + 8);
                float2 p3 = *(const float2*)(As + (size_t)(r + 8) * AROWF + kb + 2 * qcol + 8);
                a[mf][0] = bf2(p0.x, p0.y);
                a[mf][1] = bf2(p1.x, p1.y);
                a[mf][2] = bf2(p2.x, p2.y);
                a[mf][3] = bf2(p3.x, p3.y);
            }
            uint32_t b[4][2];
#pragma unroll
            for (int nf = 0; nf < 4; nf++) {
                int cc = xrow0 + nf * 8;
                b[nf][0] = *(const uint32_t*)(Xs + cc * XROWB + (kb + 2 * qcol) * 2);
                b[nf][1] = *(const uint32_t*)(Xs + cc * XROWB + (kb + 2 * qcol) * 2 + 16);
            }
#pragma unroll
            for (int mf = 0; mf < 2; mf++)
#pragma unroll
                for (int nf = 0; nf < 4; nf++)
                    mma_bf16(acc[mf][nf], a[mf], b[nf]);
        }

        if ((g & 255) == 255 || g == ge - 1) {
            int sl = c - sched_cfirst(cur_m);
            int n0 = cur_m * MT;
#pragma unroll
            for (int mf = 0; mf < 2; mf++)
#pragma unroll
                for (int nf = 0; nf < 4; nf++) {
                    int m = n0 + wm * 32 + mf * 16 + qrow;
                    int cc = wn * 32 + nf * 8 + qcol * 2;
                    float* p0 = g_part + ((size_t)sl * NNODES + m) * NC + cc;
                    *(float2*)p0 = make_float2(acc[mf][nf][0], acc[mf][nf][1]);
                    float* p1 = g_part + ((size_t)sl * NNODES + m + 8) * NC + cc;
                    *(float2*)p1 = make_float2(acc[mf][nf][2], acc[mf][nf][3]);
                    acc[mf][nf][0] = 0.0f; acc[mf][nf][1] = 0.0f;
                    acc[mf][nf][2] = 0.0f; acc[mf][nf][3] = 0.0f;
                }
            cur_m++;
        }
    }
    asm volatile("cp.async.wait_group 0;" ::: "memory");
}

// ---------------- kernel 3: DRIFT-only MLP (R14 drift path, all 256 threads) ----------------
__global__ void __launch_bounds__(256) mlp_kernel(
    const float* __restrict__ t,
    const float* __restrict__ W1f, const float* __restrict__ b1f,
    const float* __restrict__ W2f, const float* __restrict__ b2f,
    float* __restrict__ out) {
    __shared__ __align__(16) float sW1fT[64 * W1TS];
    __shared__ __align__(16) float sW2f[64 * 16];
    __shared__ float sbzf[64], sb2f[16];
    int tid = threadIdx.x;
    for (int i = tid; i < 16 * 64; i += 256) {
        int j = i & 63, r = i >> 6;
        sW1fT[j * W1TS + r] = W1f[i];
    }
    for (int i = tid; i < 64 * 16; i += 256) sW2f[i] = W2f[i];
    float tv = t[0];
    if (tid < 64) sbzf[tid] = fmaf(tv, W1f[16 * 64 + tid], b1f[tid]);
    if (tid < 16) sb2f[tid] = b2f[tid];
    __syncthreads();

    int gid = blockIdx.x * 256 + tid;           // 0..32767
    int b = gid >> 13, n = gid & (NNODES - 1);
    size_t o0 = (size_t)b * NNODES * DDIM + (size_t)n * DDIM;

    int mt = n >> 7;
    int nseg = sched_clast(mt) - sched_cfirst(mt) + 1;   // 5 or 6
    float x[16];
#pragma unroll
    for (int k = 0; k < 16; k++) x[k] = 0.0f;
    size_t base = (size_t)n * NC + (size_t)b * DDIM;
    for (int s = 0; s < nseg; s++) {
        const float4* p = (const float4*)(g_part + (size_t)s * NNODES * NC + base);
#pragma unroll
        for (int k = 0; k < 4; k++) {
            float4 a = p[k];
            x[4 * k + 0] += a.x; x[4 * k + 1] += a.y;
            x[4 * k + 2] += a.z; x[4 * k + 3] += a.w;
        }
    }

    float drift[16];
#pragma unroll
    for (int d = 0; d < 16; d++) drift[d] = sb2f[d];

#pragma unroll 4
    for (int j = 0; j < 64; j++) {
        const float4* wfr = (const float4*)(sW1fT + j * W1TS);
        float4 w0 = wfr[0], w1 = wfr[1], w2 = wfr[2], w3 = wfr[3];
        float za = fmaf(x[0], w0.x, fmaf(x[1], w0.y, fmaf(x[2], w0.z, x[3] * w0.w)));
        float zb = fmaf(x[4], w1.x, fmaf(x[5], w1.y, fmaf(x[6], w1.z, x[7] * w1.w)));
        float zc = fmaf(x[8], w2.x, fmaf(x[9], w2.y, fmaf(x[10], w2.z, x[11] * w2.w)));
        float zd = fmaf(x[12], w3.x, fmaf(x[13], w3.y, fmaf(x[14], w3.z, x[15] * w3.w)));
        float zf = (za + zb) + (zc + zd) + sbzf[j];
        float af = tanh_fast(zf);

        const float4* w2r = (const float4*)(sW2f + j * 16);
#pragma unroll
        for (int q = 0; q < 4; q++) {
            float4 cf = w2r[q];
            drift[4 * q + 0] = fmaf(af, cf.x, drift[4 * q + 0]);
            drift[4 * q + 1] = fmaf(af, cf.y, drift[4 * q + 1]);
            drift[4 * q + 2] = fmaf(af, cf.z, drift[4 * q + 2]);
            drift[4 * q + 3] = fmaf(af, cf.w, drift[4 * q + 3]);
        }
    }

    float4* od = (float4*)(out + o0);
#pragma unroll
    for (int k = 0; k < 4; k++)
        od[k] = make_float4(drift[4 * k], drift[4 * k + 1],
                            drift[4 * k + 2], drift[4 * k + 3]);
}

extern "C" void kernel_launch(void* const* d_in, const int* in_sizes, int n_in,
                              void* d_out, int out_size) {
    (void)in_sizes; (void)n_in; (void)out_size;
    const float* h   = (const float*)d_in[0];
    const float* t   = (const float*)d_in[1];
    const float* A   = (const float*)d_in[2];
    const float* W1f = (const float*)d_in[3];
    const float* b1f = (const float*)d_in[4];
    const float* W2f = (const float*)d_in[5];
    const float* b2f = (const float*)d_in[6];
    const float* W1g = (const float*)d_in[7];
    const float* b1g = (const float*)d_in[8];
    const float* W2g = (const float*)d_in[9];
    const float* b2g = (const float*)d_in[10];
    float* out = (float*)d_out;

    cudaFuncSetAttribute(gemm_kernel, cudaFuncAttributeMaxDynamicSharedMemorySize, SMEM_TOTAL);

    transpose_diff_kernel<<<128, 256>>>(h, t, W1g, b1g, W2g, b2g, out);
    gemm_kernel<<<NCTA, 256, SMEM_TOTAL>>>(A);
    mlp_kernel<<<128, 256>>>(t, W1f, b1f, W2f, b2f, out);
}

// round 17
// speedup vs baseline: 1.0640x; 1.0640x over previous
#include <cuda_runtime.h>
#include <cuda_bf16.h>
#include <cstdint>
#include <cstddef>

#define NNODES 8192
#define DDIM   16
#define BATCH  4
#define NC     64                       // B*D output columns
#define MT     128                      // M tile
#define KT     32                       // K per stage
#define NKU    256                      // k-units per m-tile (8192/32)
#define NMT    64                       // m-tiles
#define NCTA   296                      // 148 SMs x 2 CTAs, exact fit
#define SLOTS  6                        // max k-segments per m-tile
#define STAGES 4

#define AROWF  40                       // A smem row: 32 fp32 + 8 pad (160B)
#define AROWB  160
#define XROWB  80                       // X smem row: 64B bf16 + 16 pad
#define A_BYTES (MT * AROWB)            // 20480
#define X_BYTES (NC * XROWB)            // 5120
#define STAGE_BYTES (A_BYTES + X_BYTES) // 25600
#define SMEM_TOTAL  (STAGES * STAGE_BYTES) // 102400

__device__ __align__(128) __nv_bfloat16 g_XT[NC * NNODES];     // 1 MB bf16
__device__ __align__(128) float g_part[SLOTS * NNODES * NC];   // 12.6 MB

// CTA c covers global units [s(c), s(c+1)), s(c) = floor(2048*c/37)
__device__ __forceinline__ int sched_start(int c) { return (c * 2048) / 37; }
__device__ __forceinline__ int sched_cfirst(int m) { return ((9472 * m + 2084) >> 11) - 1; }
__device__ __forceinline__ int sched_clast(int m) { return ((37 * (m + 1) + 7) >> 3) - 1; }

// ---- helpers ----
__device__ __forceinline__ uint32_t smem_u32(const void* p) {
    uint32_t a;
    asm("{ .reg .u64 t; cvta.to.shared.u64 t, %1; cvt.u32.u64 %0, t; }" : "=r"(a) : "l"(p));
    return a;
}
__device__ __forceinline__ void cp_async16(uint32_t smem_dst, const void* gmem_src) {
    asm volatile("cp.async.cg.shared.global [%0], [%1], 16;" :: "r"(smem_dst), "l"(gmem_src));
}
#define CP_COMMIT() asm volatile("cp.async.commit_group;" ::: "memory")

__device__ __forceinline__ float tanh_fast(float x) {
    float r;
    asm("tanh.approx.f32 %0, %1;" : "=f"(r) : "f"(x));
    return r;
}

__device__ __forceinline__ uint32_t bf2(float lo, float hi) {
    __nv_bfloat162 v = __float22bfloat162_rn(make_float2(lo, hi));
    return *(uint32_t*)&v;
}

__device__ __forceinline__ void mma_bf16(float* c, const uint32_t* a, const uint32_t* b) {
    asm volatile(
        "mma.sync.aligned.m16n8k16.row.col.f32.bf16.bf16.f32 "
        "{%0,%1,%2,%3}, {%4,%5,%6,%7}, {%8,%9}, {%0,%1,%2,%3};"
        : "+f"(c[0]), "+f"(c[1]), "+f"(c[2]), "+f"(c[3])
        : "r"(a[0]), "r"(a[1]), "r"(a[2]), "r"(a[3]), "r"(b[0]), "r"(b[1]));
}

// ---------------- kernel 1: XT[b*16+d][m] = bf16(h[b][m*16+d])  (R14-identical) ----------------
__global__ void __launch_bounds__(256) transpose_kernel(const float* __restrict__ h) {
    __shared__ float tile[16][258];
    int tid = threadIdx.x;
    int b  = blockIdx.x >> 5;
    int m0 = (blockIdx.x & 31) << 8;    // 256 rows per block
    const float4* src = (const float4*)(h + (size_t)b * (NNODES * DDIM) + (size_t)m0 * DDIM);

    float4 v[4];
#pragma unroll
    for (int i = 0; i < 4; i++) v[i] = src[i * 256 + tid];
#pragma unroll
    for (int i = 0; i < 4; i++) {
        int j = i * 256 + tid;
        int m = j >> 2, d0 = (j & 3) * 4;
        tile[d0 + 0][m] = v[i].x;
        tile[d0 + 1][m] = v[i].y;
        tile[d0 + 2][m] = v[i].z;
        tile[d0 + 3][m] = v[i].w;
    }
    __syncthreads();
#pragma unroll
    for (int i = 0; i < 8; i++) {
        int j = i * 256 + tid;
        int d = j >> 7, mp = j & 127;
        float2 p = *(const float2*)&tile[d][2 * mp];
        __nv_bfloat162 w = __float22bfloat162_rn(p);
        *(__nv_bfloat162*)(g_XT + (size_t)(b * 16 + d) * NNODES + m0 + 2 * mp) = w;
    }
}

// ---------------- kernel 2: balanced bf16 mma GEMM -> g_part (R14-identical) ----------------
__global__ void __launch_bounds__(256, 2) gemm_kernel(const float* __restrict__ A) {
    extern __shared__ char smem[];
    uint32_t sb = smem_u32(smem);

    int tid = threadIdx.x;
    int c   = blockIdx.x;
    int gs  = sched_start(c);
    int ge  = sched_start(c + 1);

    int lane = tid & 31, wid = tid >> 5;
    int wm = wid & 3, wn = wid >> 2;
    int qrow = lane >> 2, qcol = lane & 3;

    uint32_t offA[4]; size_t aoffA[4];
#pragma unroll
    for (int i = 0; i < 4; i++) {
        int q = i * 256 + tid;
        int row = q >> 3, c16 = q & 7;
        offA[i] = (uint32_t)(row * AROWB + c16 * 16);
        aoffA[i] = (size_t)row * NNODES + (size_t)c16 * 4;
    }
    uint32_t offX; size_t xoff;
    {
        int row = tid >> 2, c16 = tid & 3;
        offX = (uint32_t)(row * XROWB + c16 * 16);
        xoff = (size_t)row * NNODES + (size_t)c16 * 8;
    }

#pragma unroll
    for (int p = 0; p < STAGES - 1; p++) {
        int g = gs + p;
        int m = g >> 8, k0 = (g & 255) * KT;
        size_t abase = (size_t)m * MT * NNODES + k0;
        uint32_t ab = sb + (g & 3) * STAGE_BYTES;
#pragma unroll
        for (int i = 0; i < 4; i++) cp_async16(ab + offA[i], A + abase + aoffA[i]);
        cp_async16(ab + A_BYTES + offX, g_XT + xoff + k0);
        CP_COMMIT();
    }

    float acc[2][4][4];
#pragma unroll
    for (int mf = 0; mf < 2; mf++)
#pragma unroll
        for (int nf = 0; nf < 4; nf++)
#pragma unroll
            for (int r = 0; r < 4; r++) acc[mf][nf][r] = 0.0f;

    const int arow0 = wm * 32 + qrow;
    const int xrow0 = wn * 32 + qrow;
    int cur_m = gs >> 8;

    for (int g = gs; g < ge; g++) {
        asm volatile("cp.async.wait_group %0;" :: "n"(STAGES - 2) : "memory");
        __syncthreads();

        int gn = g + STAGES - 1;
        if (gn < ge) {
            int m = gn >> 8, k0 = (gn & 255) * KT;
            size_t abase = (size_t)m * MT * NNODES + k0;
            uint32_t ab = sb + (gn & 3) * STAGE_BYTES;
#pragma unroll
            for (int i = 0; i < 4; i++) cp_async16(ab + offA[i], A + abase + aoffA[i]);
            cp_async16(ab + A_BYTES + offX, g_XT + xoff + k0);
        }
        CP_COMMIT();

        const float* As = (const float*)(smem + (g & 3) * STAGE_BYTES);
        const char*  Xs = smem + (g & 3) * STAGE_BYTES + A_BYTES;
#pragma unroll
        for (int kk = 0; kk < 2; kk++) {
            int kb = kk * 16;
            uint32_t a[2][4];
#pragma unroll
            for (int mf = 0; mf < 2; mf++) {
                int r = arow0 + mf * 16;
                float2 p0 = *(const float2*)(As + (size_t)r * AROWF + kb + 2 * qcol);
                float2 p1 = *(const float2*)(As + (size_t)(r + 8) * AROWF + kb + 2 * qcol);
                float2 p2 = *(const float2*)(As + (size_t)r * AROWF + kb + 2 * qcol + 8);
                float2 p3 = *(const float2*)(As + (size_t)(r + 8) * AROWF + kb + 2 * qcol + 8);
                a[mf][0] = bf2(p0.x, p0.y);
                a[mf][1] = bf2(p1.x, p1.y);
                a[mf][2] = bf2(p2.x, p2.y);
                a[mf][3] = bf2(p3.x, p3.y);
            }
            uint32_t b[4][2];
#pragma unroll
            for (int nf = 0; nf < 4; nf++) {
                int cc = xrow0 + nf * 8;
                b[nf][0] = *(const uint32_t*)(Xs + cc * XROWB + (kb + 2 * qcol) * 2);
                b[nf][1] = *(const uint32_t*)(Xs + cc * XROWB + (kb + 2 * qcol) * 2 + 16);
            }
#pragma unroll
            for (int mf = 0; mf < 2; mf++)
#pragma unroll
                for (int nf = 0; nf < 4; nf++)
                    mma_bf16(acc[mf][nf], a[mf], b[nf]);
        }

        if ((g & 255) == 255 || g == ge - 1) {
            int sl = c - sched_cfirst(cur_m);
            int n0 = cur_m * MT;
#pragma unroll
            for (int mf = 0; mf < 2; mf++)
#pragma unroll
                for (int nf = 0; nf < 4; nf++) {
                    int m = n0 + wm * 32 + mf * 16 + qrow;
                    int cc = wn * 32 + nf * 8 + qcol * 2;
                    float* p0 = g_part + ((size_t)sl * NNODES + m) * NC + cc;
                    *(float2*)p0 = make_float2(acc[mf][nf][0], acc[mf][nf][1]);
                    float* p1 = g_part + ((size_t)sl * NNODES + m + 8) * NC + cc;
                    *(float2*)p1 = make_float2(acc[mf][nf][2], acc[mf][nf][3]);
                    acc[mf][nf][0] = 0.0f; acc[mf][nf][1] = 0.0f;
                    acc[mf][nf][2] = 0.0f; acc[mf][nf][3] = 0.0f;
                }
            cur_m++;
        }
    }
    asm volatile("cp.async.wait_group 0;" ::: "memory");
}

// ---------------- kernel 3: fused MLPs, f/g split, MUFU tanh (R14 + batched x-load) ----------------
#define W1TS 20   // transposed W1 row stride (16 used here, 16B-aligned)
__global__ void __launch_bounds__(256) mlp_kernel(
    const float* __restrict__ h, const float* __restrict__ t,
    const float* __restrict__ W1f, const float* __restrict__ b1f,
    const float* __restrict__ W2f, const float* __restrict__ b2f,
    const float* __restrict__ W1g, const float* __restrict__ b1g,
    const float* __restrict__ W2g, const float* __restrict__ b2g,
    float* __restrict__ out) {
    __shared__ __align__(16) float sW1fT[64 * W1TS], sW1gT[64 * W1TS];
    __shared__ __align__(16) float sW2f[64 * 16], sW2g[64 * 16];
    __shared__ float sbzf[64], sbzg[64], sb2f[16], sb2g[16];
    int tid = threadIdx.x;
    for (int i = tid; i < 16 * 64; i += 256) {
        int j = i & 63, r = i >> 6;             // i = r*64 + j, r < 16
        sW1fT[j * W1TS + r] = W1f[i];
        sW1gT[j * W1TS + r] = W1g[i];
    }
    for (int i = tid; i < 64 * 16; i += 256) { sW2f[i] = W2f[i]; sW2g[i] = W2g[i]; }
    float tv = t[0];
    if (tid < 64) {                             // z-offset: bias + t * W1[16][j]
        sbzf[tid] = fmaf(tv, W1f[16 * 64 + tid], b1f[tid]);
        sbzg[tid] = fmaf(tv, W1g[16 * 64 + tid], b1g[tid]);
    }
    if (tid < 16) { sb2f[tid] = b2f[tid]; sb2g[tid] = b2g[tid]; }
    __syncthreads();

    int gid = blockIdx.x * 128 + (tid & 127);   // 0..32767
    bool gpath = tid >= 128;
    int b = gid >> 13, n = gid & (NNODES - 1);
    size_t o0 = (size_t)b * NNODES * DDIM + (size_t)n * DDIM;

    if (!gpath) {
        // ---- drift: x = sum of split-K partials (fully unrolled, predicated loads) ----
        int mt = n >> 7;
        int nseg = sched_clast(mt) - sched_cfirst(mt) + 1;   // 5 or 6
        size_t base = (size_t)n * NC + (size_t)b * DDIM;
        float4 seg[SLOTS][4];
#pragma unroll
        for (int s = 0; s < SLOTS; s++) {
            const float4* p = (const float4*)(g_part + (size_t)s * NNODES * NC + base);
            bool use = s < nseg;
#pragma unroll
            for (int k = 0; k < 4; k++)
                seg[s][k] = use ? p[k] : make_float4(0.f, 0.f, 0.f, 0.f);
        }
        float x[16];
#pragma unroll
        for (int k = 0; k < 4; k++) {
            x[4 * k + 0] = ((seg[0][k].x + seg[1][k].x) + (seg[2][k].x + seg[3][k].x)) + (seg[4][k].x + seg[5][k].x);
            x[4 * k + 1] = ((seg[0][k].y + seg[1][k].y) + (seg[2][k].y + seg[3][k].y)) + (seg[4][k].y + seg[5][k].y);
            x[4 * k + 2] = ((seg[0][k].z + seg[1][k].z) + (seg[2][k].z + seg[3][k].z)) + (seg[4][k].z + seg[5][k].z);
            x[4 * k + 3] = ((seg[0][k].w + seg[1][k].w) + (seg[2][k].w + seg[3][k].w)) + (seg[4][k].w + seg[5][k].w);
        }

        float drift[16];
#pragma unroll
        for (int d = 0; d < 16; d++) drift[d] = sb2f[d];

#pragma unroll 4
        for (int j = 0; j < 64; j++) {
            const float4* wfr = (const float4*)(sW1fT + j * W1TS);
            float4 w0 = wfr[0], w1 = wfr[1], w2 = wfr[2], w3 = wfr[3];
            float za = fmaf(x[0], w0.x, fmaf(x[1], w0.y, fmaf(x[2], w0.z, x[3] * w0.w)));
            float zb = fmaf(x[4], w1.x, fmaf(x[5], w1.y, fmaf(x[6], w1.z, x[7] * w1.w)));
            float zc = fmaf(x[8], w2.x, fmaf(x[9], w2.y, fmaf(x[10], w2.z, x[11] * w2.w)));
            float zd = fmaf(x[12], w3.x, fmaf(x[13], w3.y, fmaf(x[14], w3.z, x[15] * w3.w)));
            float zf = (za + zb) + (zc + zd) + sbzf[j];
            float af = tanh_fast(zf);                    // 1 MUFU

            const float4* w2r = (const float4*)(sW2f + j * 16);
#pragma unroll
            for (int q = 0; q < 4; q++) {
                float4 cf = w2r[q];
                drift[4 * q + 0] = fmaf(af, cf.x, drift[4 * q + 0]);
                drift[4 * q + 1] = fmaf(af, cf.y, drift[4 * q + 1]);
                drift[4 * q + 2] = fmaf(af, cf.z, drift[4 * q + 2]);
                drift[4 * q + 3] = fmaf(af, cf.w, drift[4 * q + 3]);
            }
        }

        float4* od = (float4*)(out + o0);
#pragma unroll
        for (int k = 0; k < 4; k++)
            od[k] = make_float4(drift[4 * k], drift[4 * k + 1],
                                drift[4 * k + 2], drift[4 * k + 3]);
    } else {
        // ---- diffusion: y = h, 2-layer sigmoid MLP, 0.1*sigmoid ----
        float y[16];
        const float4* ph = (const float4*)(h + o0);
#pragma unroll
        for (int k = 0; k < 4; k++) {
            float4 a = ph[k];
            y[4 * k + 0] = a.x; y[4 * k + 1] = a.y; y[4 * k + 2] = a.z; y[4 * k + 3] = a.w;
        }

        float dacc[16];
#pragma unroll
        for (int d = 0; d < 16; d++) dacc[d] = sb2g[d];

#pragma unroll 4
        for (int j = 0; j < 64; j++) {
            const float4* wgr = (const float4*)(sW1gT + j * W1TS);
            float4 w0 = wgr[0], w1 = wgr[1], w2 = wgr[2], w3 = wgr[3];
            float za = fmaf(y[0], w0.x, fmaf(y[1], w0.y, fmaf(y[2], w0.z, y[3] * w0.w)));
            float zb = fmaf(y[4], w1.x, fmaf(y[5], w1.y, fmaf(y[6], w1.z, y[7] * w1.w)));
            float zc = fmaf(y[8], w2.x, fmaf(y[9], w2.y, fmaf(y[10], w2.z, y[11] * w2.w)));
            float zd = fmaf(y[12], w3.x, fmaf(y[13], w3.y, fmaf(y[14], w3.z, y[15] * w3.w)));
            float zg = (za + zb) + (zc + zd) + sbzg[j];
            float ag = fmaf(0.5f, tanh_fast(0.5f * zg), 0.5f);   // sigmoid via MUFU tanh

            const float4* w2r = (const float4*)(sW2g + j * 16);
#pragma unroll
            for (int q = 0; q < 4; q++) {
                float4 cg = w2r[q];
                dacc[4 * q + 0] = fmaf(ag, cg.x, dacc[4 * q + 0]);
                dacc[4 * q + 1] = fmaf(ag, cg.y, dacc[4 * q + 1]);
                dacc[4 * q + 2] = fmaf(ag, cg.z, dacc[4 * q + 2]);
                dacc[4 * q + 3] = fmaf(ag, cg.w, dacc[4 * q + 3]);
            }
        }

        float4* og = (float4*)(out + (size_t)BATCH * NNODES * DDIM + o0);
#pragma unroll
        for (int k = 0; k < 4; k++) {
            // 0.1*sigmoid(z) = 0.05*tanh(0.5z) + 0.05
            float g0 = fmaf(0.05f, tanh_fast(0.5f * dacc[4 * k + 0]), 0.05f);
            float g1 = fmaf(0.05f, tanh_fast(0.5f * dacc[4 * k + 1]), 0.05f);
            float g2 = fmaf(0.05f, tanh_fast(0.5f * dacc[4 * k + 2]), 0.05f);
            float g3 = fmaf(0.05f, tanh_fast(0.5f * dacc[4 * k + 3]), 0.05f);
            og[k] = make_float4(g0, g1, g2, g3);
        }
    }
}

extern "C" void kernel_launch(void* const* d_in, const int* in_sizes, int n_in,
                              void* d_out, int out_size) {
    (void)in_sizes; (void)n_in; (void)out_size;
    const float* h   = (const float*)d_in[0];
    const float* t   = (const float*)d_in[1];
    const float* A   = (const float*)d_in[2];
    const float* W1f = (const float*)d_in[3];
    const float* b1f = (const float*)d_in[4];
    const float* W2f = (const float*)d_in[5];
    const float* b2f = (const float*)d_in[6];
    const float* W1g = (const float*)d_in[7];
    const float* b1g = (const float*)d_in[8];
    const float* W2g = (const float*)d_in[9];
    const float* b2g = (const float*)d_in[10];
    float* out = (float*)d_out;

    cudaFuncSetAttribute(gemm_kernel, cudaFuncAttributeMaxDynamicSharedMemorySize, SMEM_TOTAL);

    transpose_kernel<<<128, 256>>>(h);
    gemm_kernel<<<NCTA, 256, SMEM_TOTAL>>>(A);
    mlp_kernel<<<256, 256>>>(h, t, W1f, b1f, W2f, b2f, W1g, b1g, W2g, b2g, out);
}